// round 11
// baseline (speedup 1.0000x reference)
#include <cuda_runtime.h>
#include <cuda_bf16.h>
#include <math.h>

using bf16 = __nv_bfloat16;
using u32  = unsigned int;
using s64  = long long;

// ---------------------------------------------------------------------------
// Problem constants
// ---------------------------------------------------------------------------
constexpr int kB    = 2;
constexpr int kC    = 512;
constexpr int kGrp  = 32;
constexpr int kSeq  = 4096;
constexpr int kTok  = 8192;
constexpr float kEps = 1e-5f;

// ---------------------------------------------------------------------------
// GEMM tiling: 128x256 CTA tile, 64x64 warp tile, K=32 per stage, 3 stages
// ---------------------------------------------------------------------------
constexpr int TBM = 128;
constexpr int TBN = 256;
constexpr int TBK = 32;
constexpr int APAD   = TBK + 8;   // 40   (As row pitch, rows = M)
constexpr int BPAD_T = TBK + 8;   // 40   (Bs row pitch, TB: rows = N)
constexpr int BPAD_N = TBN + 8;   // 264  (Bs row pitch, non-TB: rows = K)

constexpr int STAGES = 3;
constexpr int ASZ   = TBM * APAD;     // 5120 elems / stage
constexpr int BSZ_T = TBN * BPAD_T;   // 10240
constexpr int BSZ_N = TBK * BPAD_N;   // 8448
constexpr int SMEM_BYTES_T = STAGES * (ASZ + BSZ_T) * 2;   // 92160
constexpr int SMEM_BYTES_N = STAGES * (ASZ + BSZ_N) * 2;   // 81408

// ---------------------------------------------------------------------------
// Device scratch (allocation-free rule: __device__ globals)
// ---------------------------------------------------------------------------
__device__ __align__(128) bf16 g_xn[kTok * kC];
__device__ __align__(128) bf16 g_q [kTok * kC];
__device__ __align__(128) bf16 g_k [kTok * kC];
__device__ __align__(128) bf16 g_v [kTok * kC];
__device__ __align__(128) bf16 g_o [kTok * kC];
__device__ __align__(128) bf16 g_s [(s64)kB * kSeq * kSeq];   // 64 MB
__device__ __align__(128) bf16 g_wq[kC * kC];
__device__ __align__(128) bf16 g_wk[kC * kC];
__device__ __align__(128) bf16 g_wv[kC * kC];
__device__ __align__(128) bf16 g_wp[kC * kC];
__device__ float g_mu  [kB * kGrp];
__device__ float g_rsig[kB * kGrp];

// ---------------------------------------------------------------------------
// Small helpers
// ---------------------------------------------------------------------------
__device__ __forceinline__ float warp_sum(float v) {
    #pragma unroll
    for (int o = 16; o > 0; o >>= 1) v += __shfl_xor_sync(0xffffffffu, v, o);
    return v;
}
__device__ __forceinline__ float warp_max(float v) {
    #pragma unroll
    for (int o = 16; o > 0; o >>= 1) v = fmaxf(v, __shfl_xor_sync(0xffffffffu, v, o));
    return v;
}

__device__ __forceinline__ u32 smem_u32(const void* p) {
    return (u32)__cvta_generic_to_shared(p);
}
__device__ __forceinline__ void cpasync16(u32 s, const void* g) {
    asm volatile("cp.async.cg.shared.global [%0], [%1], 16;" :: "r"(s), "l"(g));
}
__device__ __forceinline__ void cp_commit() { asm volatile("cp.async.commit_group;"); }
__device__ __forceinline__ void cp_wait0()  { asm volatile("cp.async.wait_group 0;"); }
__device__ __forceinline__ void cp_wait1()  { asm volatile("cp.async.wait_group 1;"); }

__device__ __forceinline__ void ldm_x4(u32& r0, u32& r1, u32& r2, u32& r3, u32 a) {
    asm volatile("ldmatrix.sync.aligned.m8n8.x4.shared.b16 {%0,%1,%2,%3}, [%4];"
                 : "=r"(r0), "=r"(r1), "=r"(r2), "=r"(r3) : "r"(a));
}
__device__ __forceinline__ void ldm_x2(u32& r0, u32& r1, u32 a) {
    asm volatile("ldmatrix.sync.aligned.m8n8.x2.shared.b16 {%0,%1}, [%2];"
                 : "=r"(r0), "=r"(r1) : "r"(a));
}
__device__ __forceinline__ void ldm_x2t(u32& r0, u32& r1, u32 a) {
    asm volatile("ldmatrix.sync.aligned.m8n8.x2.trans.shared.b16 {%0,%1}, [%2];"
                 : "=r"(r0), "=r"(r1) : "r"(a));
}
__device__ __forceinline__ void mma16816(float* c, const u32* a, const u32* b) {
    asm volatile(
        "mma.sync.aligned.m16n8k16.row.col.f32.bf16.bf16.f32 "
        "{%0,%1,%2,%3}, {%4,%5,%6,%7}, {%8,%9}, {%0,%1,%2,%3};"
        : "+f"(c[0]), "+f"(c[1]), "+f"(c[2]), "+f"(c[3])
        : "r"(a[0]), "r"(a[1]), "r"(a[2]), "r"(a[3]), "r"(b[0]), "r"(b[1]));
}

// ---------------------------------------------------------------------------
// GroupNorm statistics: one block per (b, g)
// ---------------------------------------------------------------------------
__global__ __launch_bounds__(256) void gn_stats_kernel(const float* __restrict__ x) {
    int bg = blockIdx.x;
    int b  = bg >> 5;
    int g  = bg & 31;
    const float* base = x + (s64)b * kSeq * kC + g * 16;

    float s = 0.f, s2 = 0.f;
    for (int t4 = threadIdx.x; t4 < kSeq * 4; t4 += 256) {
        int hw = t4 >> 2, j4 = t4 & 3;
        float4 v = *(const float4*)(base + (s64)hw * kC + j4 * 4);
        s  += v.x + v.y + v.z + v.w;
        s2 += v.x*v.x + v.y*v.y + v.z*v.z + v.w*v.w;
    }
    __shared__ float sh_s[8], sh_s2[8];
    int lane = threadIdx.x & 31, wid = threadIdx.x >> 5;
    s = warp_sum(s); s2 = warp_sum(s2);
    if (lane == 0) { sh_s[wid] = s; sh_s2[wid] = s2; }
    __syncthreads();
    if (wid == 0) {
        s  = (lane < 8) ? sh_s[lane]  : 0.f;
        s2 = (lane < 8) ? sh_s2[lane] : 0.f;
        s = warp_sum(s); s2 = warp_sum(s2);
        if (lane == 0) {
            float inv = 1.0f / (float)(kSeq * 16);
            float m = s * inv;
            float var = s2 * inv - m * m;
            g_mu[bg]   = m;
            g_rsig[bg] = rsqrtf(var + kEps);
        }
    }
}

// ---------------------------------------------------------------------------
// GroupNorm apply -> bf16 xn
// ---------------------------------------------------------------------------
__global__ __launch_bounds__(256) void gn_apply_kernel(
    const float* __restrict__ x, const float* __restrict__ gamma,
    const float* __restrict__ beta)
{
    s64 i4 = (s64)blockIdx.x * 256 + threadIdx.x;   // float4 index
    int c4 = (int)(i4 & 127);
    int b  = (int)(i4 >> 19);
    int g  = c4 >> 2;
    float m = g_mu[b * kGrp + g];
    float r = g_rsig[b * kGrp + g];
    float4 xv = ((const float4*)x)[i4];
    float4 gv = ((const float4*)gamma)[c4];
    float4 bv = ((const float4*)beta)[c4];
    float o0 = (xv.x - m) * r * gv.x + bv.x;
    float o1 = (xv.y - m) * r * gv.y + bv.y;
    float o2 = (xv.z - m) * r * gv.z + bv.z;
    float o3 = (xv.w - m) * r * gv.w + bv.w;
    __nv_bfloat162 p0 = __floats2bfloat162_rn(o0, o1);
    __nv_bfloat162 p1 = __floats2bfloat162_rn(o2, o3);
    uint2 pk;
    pk.x = *(u32*)&p0;
    pk.y = *(u32*)&p1;
    ((uint2*)g_xn)[i4] = pk;
}

// ---------------------------------------------------------------------------
// fp32 -> bf16 conversion (weights); blockIdx.y selects which of 4 weights
// ---------------------------------------------------------------------------
__global__ __launch_bounds__(256) void f2bf_kernel(
    const float* __restrict__ w0, const float* __restrict__ w1,
    const float* __restrict__ w2, const float* __restrict__ w3)
{
    const float* src = (blockIdx.y == 0) ? w0 : (blockIdx.y == 1) ? w1
                     : (blockIdx.y == 2) ? w2 : w3;
    bf16* dst = (blockIdx.y == 0) ? g_wq : (blockIdx.y == 1) ? g_wk
              : (blockIdx.y == 2) ? g_wv : g_wp;
    s64 i4 = (s64)blockIdx.x * 256 + threadIdx.x;
    float4 v = ((const float4*)src)[i4];
    __nv_bfloat162 p0 = __floats2bfloat162_rn(v.x, v.y);
    __nv_bfloat162 p1 = __floats2bfloat162_rn(v.z, v.w);
    uint2 pk;
    pk.x = *(u32*)&p0;
    pk.y = *(u32*)&p1;
    ((uint2*)dst)[i4] = pk;
}

// ---------------------------------------------------------------------------
// Stage loader (flat smem): As [128][40], Bs TB [256][40] / non-TB [32][264]
// ---------------------------------------------------------------------------
template<bool TB>
__device__ __forceinline__ void load_stage_fn(
    bf16* As, bf16* Bs, const bf16* A, const bf16* B,
    int m0, int n0, int K, int N, int k0, int tid)
{
    #pragma unroll
    for (int i = 0; i < 2; i++) {
        int c = tid + 256 * i;                 // 512 16B chunks cover 128x32
        int r = c >> 2, cc = c & 3;
        cpasync16(smem_u32(As + r * APAD + cc * 8),
                  A + (s64)(m0 + r) * K + k0 + cc * 8);
    }
    #pragma unroll
    for (int i = 0; i < 4; i++) {
        int c = tid + 256 * i;                 // 1024 chunks cover 256x32 / 32x256
        if (TB) {
            int r = c >> 2, cc = c & 3;        // r: n-row (0..255), cc: k-chunk
            cpasync16(smem_u32(Bs + r * BPAD_T + cc * 8),
                      B + (s64)(n0 + r) * K + k0 + cc * 8);
        } else {
            int r = c >> 5, cc = c & 31;       // r: k-row (0..31), cc: n-chunk
            cpasync16(smem_u32(Bs + r * BPAD_N + cc * 8),
                      B + (s64)(k0 + r) * N + n0 + cc * 8);
        }
    }
    cp_commit();
}

// ---------------------------------------------------------------------------
// GEMM body: C = alpha * A @ op(B) [+ bias] [+ resid]
//   A: [M,K] bf16 row-major.  B: TB ? [N,K] : [K,N] bf16 row-major.
//   128x256x32 CTA tile, 256 threads = 2(M) x 4(N) warps, 64x64 per warp.
//   3-stage cp.async ring, one __syncthreads per K-tile. Dynamic smem.
// ---------------------------------------------------------------------------
extern __shared__ bf16 dynsmem[];

template<bool TB, bool OUTBF>
__device__ __forceinline__ void gemm_body(
    const bf16* A, const bf16* B,
    const float* bias, const float* resid, void* Cout,
    int bz, int M, int N, int K, float alpha, s64 sA, s64 sB, s64 sC)
{
    constexpr int BSZ = TB ? BSZ_T : BSZ_N;
    constexpr int BP  = TB ? BPAD_T : BPAD_N;
    bf16* As = dynsmem;
    bf16* Bs = dynsmem + STAGES * ASZ;

    A += bz * sA;
    B += bz * sB;

    int m0 = blockIdx.y * TBM;
    int n0 = blockIdx.x * TBN;
    int tid = threadIdx.x;
    int lane = tid & 31, wid = tid >> 5;
    int wm = wid & 1;          // 2 warps along M (64 rows each)
    int wn = wid >> 1;         // 4 warps along N (64 cols each)

    float acc[4][8][4];
    #pragma unroll
    for (int i = 0; i < 4; i++)
        #pragma unroll
        for (int j = 0; j < 8; j++)
            #pragma unroll
            for (int q = 0; q < 4; q++) acc[i][j][q] = 0.f;

    const int KT = K / TBK;    // >= 16 for every call here

    // prologue: stages 0 and 1 in flight
    load_stage_fn<TB>(As, Bs, A, B, m0, n0, K, N, 0, tid);
    load_stage_fn<TB>(As + ASZ, Bs + BSZ, A, B, m0, n0, K, N, TBK, tid);
    cp_wait1();                // stage 0 complete
    __syncthreads();

    int cur = 0;
    for (int kt = 0; kt < KT; kt++) {
        bool issue = (kt + 2 < KT);
        if (issue) {
            int nx = cur + 2; if (nx >= STAGES) nx -= STAGES;
            load_stage_fn<TB>(As + nx * ASZ, Bs + nx * BSZ, A, B,
                              m0, n0, K, N, (kt + 2) * TBK, tid);
        }

        const bf16* as = As + cur * ASZ;
        const bf16* bs = Bs + cur * BSZ;

        #pragma unroll
        for (int ks = 0; ks < 2; ks++) {
            u32 a[4][4];
            #pragma unroll
            for (int mf = 0; mf < 4; mf++) {
                int row = wm * 64 + mf * 16 + (lane & 15);
                int col = ks * 16 + ((lane >> 4) << 3);
                ldm_x4(a[mf][0], a[mf][1], a[mf][2], a[mf][3],
                       smem_u32(as + row * APAD + col));
            }
            u32 b[8][2];
            #pragma unroll
            for (int nf = 0; nf < 8; nf++) {
                if (TB) {
                    int row = wn * 64 + nf * 8 + (lane & 7);
                    int col = ks * 16 + ((lane >> 3) & 1) * 8;
                    ldm_x2(b[nf][0], b[nf][1], smem_u32(bs + row * BP + col));
                } else {
                    int row = ks * 16 + (lane & 15);
                    int col = wn * 64 + nf * 8;
                    ldm_x2t(b[nf][0], b[nf][1], smem_u32(bs + row * BP + col));
                }
            }
            #pragma unroll
            for (int mf = 0; mf < 4; mf++)
                #pragma unroll
                for (int nf = 0; nf < 8; nf++)
                    mma16816(acc[mf][nf], a[mf], b[nf]);
        }

        if (issue) cp_wait1(); else cp_wait0();
        __syncthreads();
        cur++; if (cur >= STAGES) cur = 0;
    }

    // ---- epilogue ----
    #pragma unroll
    for (int mf = 0; mf < 4; mf++) {
        #pragma unroll
        for (int nf = 0; nf < 8; nf++) {
            int r0 = m0 + wm * 64 + mf * 16 + (lane >> 2);
            int c  = n0 + wn * 64 + nf * 8 + ((lane & 3) << 1);
            float bx = 0.f, by = 0.f;
            if (bias) { bx = bias[c]; by = bias[c + 1]; }
            #pragma unroll
            for (int h = 0; h < 2; h++) {
                int m = r0 + h * 8;
                float v0 = acc[mf][nf][h * 2 + 0] * alpha + bx;
                float v1 = acc[mf][nf][h * 2 + 1] * alpha + by;
                s64 off = (s64)m * N + c;
                if (OUTBF) {
                    __nv_bfloat162 p = __floats2bfloat162_rn(v0, v1);
                    *(u32*)((bf16*)Cout + bz * sC + off) = *(u32*)&p;
                } else {
                    if (resid) {
                        float2 rv = *(const float2*)(resid + bz * sC + off);
                        v0 += rv.x; v1 += rv.y;
                    }
                    float2 o2; o2.x = v0; o2.y = v1;
                    *(float2*)((float*)Cout + bz * sC + off) = o2;
                }
            }
        }
    }
}

// ---------------------------------------------------------------------------
// Concrete kernels (plain names at launch sites)
// ---------------------------------------------------------------------------
// Fused Q/K/V projections: blockIdx.z selects which projection
__global__ __launch_bounds__(256, 1) void gemm_qkv(
    const bf16* xn,
    const bf16* wq, const bf16* wk, const bf16* wv,
    const float* bq, const float* bk, const float* bv,
    bf16* q, bf16* k, bf16* v)
{
    const bf16* W = (blockIdx.z == 0) ? wq : (blockIdx.z == 1) ? wk : wv;
    const float* bias = (blockIdx.z == 0) ? bq : (blockIdx.z == 1) ? bk : bv;
    bf16* out = (blockIdx.z == 0) ? q : (blockIdx.z == 1) ? k : v;
    gemm_body<false, true>(xn, W, bias, nullptr, out, 0,
                           kTok, kC, kC, 1.0f, 0, 0, 0);
}

__global__ __launch_bounds__(256, 1) void gemm_nt_bf(
    const bf16* A, const bf16* B, const float* bias, bf16* C,
    int M, int N, int K, float alpha, s64 sA, s64 sB, s64 sC)
{
    gemm_body<false, true>(A, B, bias, nullptr, C, blockIdx.z,
                           M, N, K, alpha, sA, sB, sC);
}

__global__ __launch_bounds__(256, 1) void gemm_tt_bf(
    const bf16* A, const bf16* B, bf16* C,
    int M, int N, int K, float alpha, s64 sA, s64 sB, s64 sC)
{
    gemm_body<true, true>(A, B, nullptr, nullptr, C, blockIdx.z,
                          M, N, K, alpha, sA, sB, sC);
}

__global__ __launch_bounds__(256, 1) void gemm_nt_f32(
    const bf16* A, const bf16* B, const float* bias, const float* resid, float* C,
    int M, int N, int K, float alpha, s64 sA, s64 sB, s64 sC)
{
    gemm_body<false, false>(A, B, bias, resid, C, blockIdx.z,
                            M, N, K, alpha, sA, sB, sC);
}

// ---------------------------------------------------------------------------
// Row softmax over bf16 S (in-place), rows of 4096
// ---------------------------------------------------------------------------
__global__ __launch_bounds__(256) void softmax_kernel() {
    s64 row = blockIdx.x;
    uint4* p = (uint4*)(g_s + row * (s64)kSeq);
    int tid = threadIdx.x;

    uint4 raw[2];
    float vals[16];
    float mx = -1e30f;
    #pragma unroll
    for (int j = 0; j < 2; j++) {
        raw[j] = p[tid + 256 * j];
        const u32* w = (const u32*)&raw[j];
        #pragma unroll
        for (int q = 0; q < 4; q++) {
            float2 f = __bfloat1622float2(*(const __nv_bfloat162*)&w[q]);
            vals[j * 8 + q * 2 + 0] = f.x;
            vals[j * 8 + q * 2 + 1] = f.y;
            mx = fmaxf(mx, fmaxf(f.x, f.y));
        }
    }
    __shared__ float sh[8];
    int lane = tid & 31, wid = tid >> 5;
    mx = warp_max(mx);
    if (lane == 0) sh[wid] = mx;
    __syncthreads();
    mx = (lane < 8) ? sh[lane] : -1e30f;
    mx = warp_max(mx);
    mx = __shfl_sync(0xffffffffu, mx, 0);
    __syncthreads();

    float sum = 0.f;
    #pragma unroll
    for (int i = 0; i < 16; i++) {
        vals[i] = __expf(vals[i] - mx);
        sum += vals[i];
    }
    sum = warp_sum(sum);
    if (lane == 0) sh[wid] = sum;
    __syncthreads();
    sum = (lane < 8) ? sh[lane] : 0.f;
    sum = warp_sum(sum);
    sum = __shfl_sync(0xffffffffu, sum, 0);
    float inv = 1.0f / sum;

    #pragma unroll
    for (int j = 0; j < 2; j++) {
        u32* w = (u32*)&raw[j];
        #pragma unroll
        for (int q = 0; q < 4; q++) {
            __nv_bfloat162 pk = __floats2bfloat162_rn(
                vals[j * 8 + q * 2 + 0] * inv, vals[j * 8 + q * 2 + 1] * inv);
            w[q] = *(u32*)&pk;
        }
        p[tid + 256 * j] = raw[j];
    }
}

// ---------------------------------------------------------------------------
// Host orchestration
// ---------------------------------------------------------------------------
extern "C" void kernel_launch(void* const* d_in, const int* in_sizes, int n_in,
                              void* d_out, int out_size)
{
    const float* x     = (const float*)d_in[0];
    const float* gamma = (const float*)d_in[1];
    const float* beta  = (const float*)d_in[2];
    const float* Wq    = (const float*)d_in[3];
    const float* bq    = (const float*)d_in[4];
    const float* Wk    = (const float*)d_in[5];
    const float* bk    = (const float*)d_in[6];
    const float* Wv    = (const float*)d_in[7];
    const float* bv    = (const float*)d_in[8];
    const float* Wp    = (const float*)d_in[9];
    const float* bp    = (const float*)d_in[10];
    float* out = (float*)d_out;

    bf16 *p_xn = 0, *p_q = 0, *p_k = 0, *p_v = 0, *p_o = 0, *p_s = 0;
    bf16 *p_wq = 0, *p_wk = 0, *p_wv = 0, *p_wp = 0;
    cudaGetSymbolAddress((void**)&p_xn, g_xn);
    cudaGetSymbolAddress((void**)&p_q,  g_q);
    cudaGetSymbolAddress((void**)&p_k,  g_k);
    cudaGetSymbolAddress((void**)&p_v,  g_v);
    cudaGetSymbolAddress((void**)&p_o,  g_o);
    cudaGetSymbolAddress((void**)&p_s,  g_s);
    cudaGetSymbolAddress((void**)&p_wq, g_wq);
    cudaGetSymbolAddress((void**)&p_wk, g_wk);
    cudaGetSymbolAddress((void**)&p_wv, g_wv);
    cudaGetSymbolAddress((void**)&p_wp, g_wp);

    // opt-in dynamic smem above 48KB (host-side attr; not a stream op)
    cudaFuncSetAttribute(gemm_qkv,    cudaFuncAttributeMaxDynamicSharedMemorySize, SMEM_BYTES_N);
    cudaFuncSetAttribute(gemm_nt_bf,  cudaFuncAttributeMaxDynamicSharedMemorySize, SMEM_BYTES_N);
    cudaFuncSetAttribute(gemm_tt_bf,  cudaFuncAttributeMaxDynamicSharedMemorySize, SMEM_BYTES_T);
    cudaFuncSetAttribute(gemm_nt_f32, cudaFuncAttributeMaxDynamicSharedMemorySize, SMEM_BYTES_N);

    const s64 seqC = (s64)kSeq * kC;
    const s64 seqS = (s64)kSeq * kSeq;

    // 1) GroupNorm (+ bf16 conversion) and weight conversions
    gn_stats_kernel<<<kB * kGrp, 256>>>(x);
    gn_apply_kernel<<<(kTok * kC / 4) / 256, 256>>>(x, gamma, beta);
    dim3 gw((kC * kC / 4) / 256, 4, 1);
    f2bf_kernel<<<gw, 256>>>(Wq, Wk, Wv, Wp);

    // 2) Q, K, V projections fused into one launch (z selects projection)
    dim3 gqkv(kC / TBN, kTok / TBM, 3);
    gemm_qkv<<<gqkv, 256, SMEM_BYTES_N>>>(p_xn, p_wq, p_wk, p_wv,
                                          bq, bk, bv, p_q, p_k, p_v);

    // 3) S = Q @ K^T * 1/sqrt(C) per batch -> bf16
    const float scale = 0.044194173824159216f;   // 1/sqrt(512)
    dim3 gqk(kSeq / TBN, kSeq / TBM, kB);
    gemm_tt_bf<<<gqk, 256, SMEM_BYTES_T>>>(p_q, p_k, p_s, kSeq, kSeq, kC, scale,
                                           seqC, seqC, seqS);

    // 4) softmax rows (bf16 in-place)
    softmax_kernel<<<kB * kSeq, 256>>>();

    // 5) O = P @ V per batch -> bf16
    dim3 gpv(kC / TBN, kSeq / TBM, kB);
    gemm_nt_bf<<<gpv, 256, SMEM_BYTES_N>>>(p_s, p_v, nullptr, p_o,
                                           kSeq, kC, kSeq, 1.0f,
                                           seqS, seqC, seqC);

    // 6) out = O @ Wp + bp + inputs (fp32)
    dim3 gproj(kC / TBN, kTok / TBM, 1);
    gemm_nt_f32<<<gproj, 256, SMEM_BYTES_N>>>(p_o, p_wp, bp, x, out,
                                              kTok, kC, kC, 1.0f, 0, 0, 0);
}

// round 12
// speedup vs baseline: 1.0949x; 1.0949x over previous
#include <cuda_runtime.h>
#include <cuda_bf16.h>
#include <math.h>

using bf16 = __nv_bfloat16;
using u32  = unsigned int;
using s64  = long long;

// ---------------------------------------------------------------------------
// Problem constants
// ---------------------------------------------------------------------------
constexpr int kB    = 2;
constexpr int kC    = 512;
constexpr int kGrp  = 32;
constexpr int kSeq  = 4096;
constexpr int kTok  = 8192;
constexpr float kEps = 1e-5f;

// ---------------------------------------------------------------------------
// GEMM tiling: 128x128 CTA tile, 64x32 warp tile, K=32/stage, 4 stages
// ---------------------------------------------------------------------------
constexpr int TBM = 128;
constexpr int TBN = 128;
constexpr int TBK = 32;
constexpr int APAD   = TBK + 8;   // 40
constexpr int BPAD_T = TBK + 8;   // 40  (TB: rows = N)
constexpr int BPAD_N = TBN + 8;   // 136 (non-TB: rows = K)

constexpr int STAGES = 4;
constexpr int ASZ   = TBM * APAD;     // 5120 elems / stage
constexpr int BSZ_T = TBN * BPAD_T;   // 5120
constexpr int BSZ_N = TBK * BPAD_N;   // 4352
constexpr int SMEM_BYTES_T = STAGES * (ASZ + BSZ_T) * 2;   // 81920
constexpr int SMEM_BYTES_N = STAGES * (ASZ + BSZ_N) * 2;   // 75776

// ---------------------------------------------------------------------------
// Device scratch (allocation-free rule: __device__ globals)
// ---------------------------------------------------------------------------
__device__ __align__(128) bf16 g_xn[kTok * kC];
__device__ __align__(128) bf16 g_q [kTok * kC];
__device__ __align__(128) bf16 g_k [kTok * kC];
__device__ __align__(128) bf16 g_v [kTok * kC];
__device__ __align__(128) bf16 g_o [kTok * kC];
__device__ __align__(128) bf16 g_s [(s64)kB * kSeq * kSeq];   // 64 MB
__device__ __align__(128) bf16 g_wq[kC * kC];
__device__ __align__(128) bf16 g_wk[kC * kC];
__device__ __align__(128) bf16 g_wv[kC * kC];
__device__ __align__(128) bf16 g_wp[kC * kC];
__device__ float g_mu  [kB * kGrp];
__device__ float g_rsig[kB * kGrp];

// ---------------------------------------------------------------------------
// Small helpers
// ---------------------------------------------------------------------------
__device__ __forceinline__ float warp_sum(float v) {
    #pragma unroll
    for (int o = 16; o > 0; o >>= 1) v += __shfl_xor_sync(0xffffffffu, v, o);
    return v;
}
__device__ __forceinline__ float warp_max(float v) {
    #pragma unroll
    for (int o = 16; o > 0; o >>= 1) v = fmaxf(v, __shfl_xor_sync(0xffffffffu, v, o));
    return v;
}

__device__ __forceinline__ u32 smem_u32(const void* p) {
    return (u32)__cvta_generic_to_shared(p);
}
__device__ __forceinline__ void cpasync16(u32 s, const void* g) {
    asm volatile("cp.async.cg.shared.global [%0], [%1], 16;" :: "r"(s), "l"(g));
}
__device__ __forceinline__ void cp_commit() { asm volatile("cp.async.commit_group;"); }
__device__ __forceinline__ void cp_wait0()  { asm volatile("cp.async.wait_group 0;"); }
__device__ __forceinline__ void cp_wait1()  { asm volatile("cp.async.wait_group 1;"); }
__device__ __forceinline__ void cp_wait2()  { asm volatile("cp.async.wait_group 2;"); }

__device__ __forceinline__ void ldm_x4(u32& r0, u32& r1, u32& r2, u32& r3, u32 a) {
    asm volatile("ldmatrix.sync.aligned.m8n8.x4.shared.b16 {%0,%1,%2,%3}, [%4];"
                 : "=r"(r0), "=r"(r1), "=r"(r2), "=r"(r3) : "r"(a));
}
__device__ __forceinline__ void ldm_x2(u32& r0, u32& r1, u32 a) {
    asm volatile("ldmatrix.sync.aligned.m8n8.x2.shared.b16 {%0,%1}, [%2];"
                 : "=r"(r0), "=r"(r1) : "r"(a));
}
__device__ __forceinline__ void ldm_x2t(u32& r0, u32& r1, u32 a) {
    asm volatile("ldmatrix.sync.aligned.m8n8.x2.trans.shared.b16 {%0,%1}, [%2];"
                 : "=r"(r0), "=r"(r1) : "r"(a));
}
__device__ __forceinline__ void mma16816(float* c, const u32* a, const u32* b) {
    asm volatile(
        "mma.sync.aligned.m16n8k16.row.col.f32.bf16.bf16.f32 "
        "{%0,%1,%2,%3}, {%4,%5,%6,%7}, {%8,%9}, {%0,%1,%2,%3};"
        : "+f"(c[0]), "+f"(c[1]), "+f"(c[2]), "+f"(c[3])
        : "r"(a[0]), "r"(a[1]), "r"(a[2]), "r"(a[3]), "r"(b[0]), "r"(b[1]));
}

// ---------------------------------------------------------------------------
// GroupNorm statistics: one block per (b, g)
// ---------------------------------------------------------------------------
__global__ __launch_bounds__(256) void gn_stats_kernel(const float* __restrict__ x) {
    int bg = blockIdx.x;
    int b  = bg >> 5;
    int g  = bg & 31;
    const float* base = x + (s64)b * kSeq * kC + g * 16;

    float s = 0.f, s2 = 0.f;
    for (int t4 = threadIdx.x; t4 < kSeq * 4; t4 += 256) {
        int hw = t4 >> 2, j4 = t4 & 3;
        float4 v = *(const float4*)(base + (s64)hw * kC + j4 * 4);
        s  += v.x + v.y + v.z + v.w;
        s2 += v.x*v.x + v.y*v.y + v.z*v.z + v.w*v.w;
    }
    __shared__ float sh_s[8], sh_s2[8];
    int lane = threadIdx.x & 31, wid = threadIdx.x >> 5;
    s = warp_sum(s); s2 = warp_sum(s2);
    if (lane == 0) { sh_s[wid] = s; sh_s2[wid] = s2; }
    __syncthreads();
    if (wid == 0) {
        s  = (lane < 8) ? sh_s[lane]  : 0.f;
        s2 = (lane < 8) ? sh_s2[lane] : 0.f;
        s = warp_sum(s); s2 = warp_sum(s2);
        if (lane == 0) {
            float inv = 1.0f / (float)(kSeq * 16);
            float m = s * inv;
            float var = s2 * inv - m * m;
            g_mu[bg]   = m;
            g_rsig[bg] = rsqrtf(var + kEps);
        }
    }
}

// ---------------------------------------------------------------------------
// GroupNorm apply -> bf16 xn
// ---------------------------------------------------------------------------
__global__ __launch_bounds__(256) void gn_apply_kernel(
    const float* __restrict__ x, const float* __restrict__ gamma,
    const float* __restrict__ beta)
{
    s64 i4 = (s64)blockIdx.x * 256 + threadIdx.x;   // float4 index
    int c4 = (int)(i4 & 127);
    int b  = (int)(i4 >> 19);
    int g  = c4 >> 2;
    float m = g_mu[b * kGrp + g];
    float r = g_rsig[b * kGrp + g];
    float4 xv = ((const float4*)x)[i4];
    float4 gv = ((const float4*)gamma)[c4];
    float4 bv = ((const float4*)beta)[c4];
    float o0 = (xv.x - m) * r * gv.x + bv.x;
    float o1 = (xv.y - m) * r * gv.y + bv.y;
    float o2 = (xv.z - m) * r * gv.z + bv.z;
    float o3 = (xv.w - m) * r * gv.w + bv.w;
    __nv_bfloat162 p0 = __floats2bfloat162_rn(o0, o1);
    __nv_bfloat162 p1 = __floats2bfloat162_rn(o2, o3);
    uint2 pk;
    pk.x = *(u32*)&p0;
    pk.y = *(u32*)&p1;
    ((uint2*)g_xn)[i4] = pk;
}

// ---------------------------------------------------------------------------
// fp32 -> bf16 conversion (weights); blockIdx.y selects which of 4 weights
// ---------------------------------------------------------------------------
__global__ __launch_bounds__(256) void f2bf_kernel(
    const float* __restrict__ w0, const float* __restrict__ w1,
    const float* __restrict__ w2, const float* __restrict__ w3)
{
    const float* src = (blockIdx.y == 0) ? w0 : (blockIdx.y == 1) ? w1
                     : (blockIdx.y == 2) ? w2 : w3;
    bf16* dst = (blockIdx.y == 0) ? g_wq : (blockIdx.y == 1) ? g_wk
              : (blockIdx.y == 2) ? g_wv : g_wp;
    s64 i4 = (s64)blockIdx.x * 256 + threadIdx.x;
    float4 v = ((const float4*)src)[i4];
    __nv_bfloat162 p0 = __floats2bfloat162_rn(v.x, v.y);
    __nv_bfloat162 p1 = __floats2bfloat162_rn(v.z, v.w);
    uint2 pk;
    pk.x = *(u32*)&p0;
    pk.y = *(u32*)&p1;
    ((uint2*)dst)[i4] = pk;
}

// ---------------------------------------------------------------------------
// Stage loader (flat smem): As [128][40], Bs TB [128][40] / non-TB [32][136]
// ---------------------------------------------------------------------------
template<bool TB>
__device__ __forceinline__ void load_stage_fn(
    bf16* As, bf16* Bs, const bf16* A, const bf16* B,
    int m0, int n0, int K, int N, int k0, int tid)
{
    #pragma unroll
    for (int i = 0; i < 2; i++) {
        int c = tid + 256 * i;                 // 512 16B chunks cover 128x32
        int r = c >> 2, cc = c & 3;
        cpasync16(smem_u32(As + r * APAD + cc * 8),
                  A + (s64)(m0 + r) * K + k0 + cc * 8);
    }
    #pragma unroll
    for (int i = 0; i < 2; i++) {
        int c = tid + 256 * i;
        if (TB) {
            int r = c >> 2, cc = c & 3;        // r: n-row, cc: k-chunk
            cpasync16(smem_u32(Bs + r * BPAD_T + cc * 8),
                      B + (s64)(n0 + r) * K + k0 + cc * 8);
        } else {
            int r = c >> 4, cc = c & 15;       // r: k-row, cc: n-chunk
            cpasync16(smem_u32(Bs + r * BPAD_N + cc * 8),
                      B + (s64)(k0 + r) * N + n0 + cc * 8);
        }
    }
    cp_commit();
}

// ---------------------------------------------------------------------------
// GEMM body: C = alpha * A @ op(B) [+ bias] [+ resid]
//   A: [M,K] bf16 row-major.  B: TB ? [N,K] : [K,N] bf16 row-major.
//   128x128x32 CTA tile, 256 threads = 2(M) x 4(N) warps, 64x32 per warp.
//   4-stage cp.async ring, one __syncthreads per K-tile. Dynamic smem.
// ---------------------------------------------------------------------------
extern __shared__ bf16 dynsmem[];

template<bool TB, bool OUTBF>
__device__ __forceinline__ void gemm_body(
    const bf16* A, const bf16* B,
    const float* bias, const float* resid, void* Cout,
    int bz, int M, int N, int K, float alpha, s64 sA, s64 sB, s64 sC)
{
    constexpr int BSZ = TB ? BSZ_T : BSZ_N;
    constexpr int BP  = TB ? BPAD_T : BPAD_N;
    bf16* As = dynsmem;
    bf16* Bs = dynsmem + STAGES * ASZ;

    A += bz * sA;
    B += bz * sB;

    int m0 = blockIdx.y * TBM;
    int n0 = blockIdx.x * TBN;
    int tid = threadIdx.x;
    int lane = tid & 31, wid = tid >> 5;
    int wm = wid & 1;          // 2 warps along M (64 rows each)
    int wn = wid >> 1;         // 4 warps along N (32 cols each)

    float acc[4][4][4];
    #pragma unroll
    for (int i = 0; i < 4; i++)
        #pragma unroll
        for (int j = 0; j < 4; j++)
            #pragma unroll
            for (int q = 0; q < 4; q++) acc[i][j][q] = 0.f;

    const int KT = K / TBK;    // 16 or 128 for every call here (>= STAGES)

    // prologue: stages 0,1,2 in flight
    load_stage_fn<TB>(As, Bs, A, B, m0, n0, K, N, 0, tid);
    load_stage_fn<TB>(As + ASZ, Bs + BSZ, A, B, m0, n0, K, N, TBK, tid);
    load_stage_fn<TB>(As + 2 * ASZ, Bs + 2 * BSZ, A, B, m0, n0, K, N, 2 * TBK, tid);
    cp_wait2();                // stage 0 complete
    __syncthreads();

    int cur = 0;
    for (int kt = 0; kt < KT; kt++) {
        // issue loads for stage kt+3 (overwrites buffer of stage kt-1; all
        // warps passed the previous barrier, so that stage is done)
        if (kt + 3 < KT) {
            int nx = cur + 3; if (nx >= STAGES) nx -= STAGES;
            load_stage_fn<TB>(As + nx * ASZ, Bs + nx * BSZ, A, B,
                              m0, n0, K, N, (kt + 3) * TBK, tid);
        }

        const bf16* as = As + cur * ASZ;
        const bf16* bs = Bs + cur * BSZ;

        #pragma unroll
        for (int ks = 0; ks < 2; ks++) {
            u32 a[4][4];
            #pragma unroll
            for (int mf = 0; mf < 4; mf++) {
                int row = wm * 64 + mf * 16 + (lane & 15);
                int col = ks * 16 + ((lane >> 4) << 3);
                ldm_x4(a[mf][0], a[mf][1], a[mf][2], a[mf][3],
                       smem_u32(as + row * APAD + col));
            }
            u32 b[4][2];
            #pragma unroll
            for (int nf = 0; nf < 4; nf++) {
                if (TB) {
                    int row = wn * 32 + nf * 8 + (lane & 7);
                    int col = ks * 16 + ((lane >> 3) & 1) * 8;
                    ldm_x2(b[nf][0], b[nf][1], smem_u32(bs + row * BP + col));
                } else {
                    int row = ks * 16 + (lane & 15);
                    int col = wn * 32 + nf * 8;
                    ldm_x2t(b[nf][0], b[nf][1], smem_u32(bs + row * BP + col));
                }
            }
            #pragma unroll
            for (int mf = 0; mf < 4; mf++)
                #pragma unroll
                for (int nf = 0; nf < 4; nf++)
                    mma16816(acc[mf][nf], a[mf], b[nf]);
        }

        // ensure stage kt+1 resident: allowed outstanding = min(2, KT-kt-2)
        if (kt + 1 < KT) {
            int rem = KT - kt - 2;
            if (rem >= 2) cp_wait2();
            else if (rem == 1) cp_wait1();
            else cp_wait0();
            __syncthreads();
        }
        cur++; if (cur >= STAGES) cur = 0;
    }

    // ---- epilogue ----
    #pragma unroll
    for (int mf = 0; mf < 4; mf++) {
        #pragma unroll
        for (int nf = 0; nf < 4; nf++) {
            int r0 = m0 + wm * 64 + mf * 16 + (lane >> 2);
            int c  = n0 + wn * 32 + nf * 8 + ((lane & 3) << 1);
            float bx = 0.f, by = 0.f;
            if (bias) { bx = bias[c]; by = bias[c + 1]; }
            #pragma unroll
            for (int h = 0; h < 2; h++) {
                int m = r0 + h * 8;
                float v0 = acc[mf][nf][h * 2 + 0] * alpha + bx;
                float v1 = acc[mf][nf][h * 2 + 1] * alpha + by;
                s64 off = (s64)m * N + c;
                if (OUTBF) {
                    __nv_bfloat162 p = __floats2bfloat162_rn(v0, v1);
                    *(u32*)((bf16*)Cout + bz * sC + off) = *(u32*)&p;
                } else {
                    if (resid) {
                        float2 rv = *(const float2*)(resid + bz * sC + off);
                        v0 += rv.x; v1 += rv.y;
                    }
                    float2 o2; o2.x = v0; o2.y = v1;
                    *(float2*)((float*)Cout + bz * sC + off) = o2;
                }
            }
        }
    }
}

// ---------------------------------------------------------------------------
// Concrete kernels (plain names at launch sites)
// ---------------------------------------------------------------------------
// Fused Q/K/V projections: blockIdx.z selects which projection
__global__ __launch_bounds__(256, 2) void gemm_qkv(
    const bf16* xn,
    const bf16* wq, const bf16* wk, const bf16* wv,
    const float* bq, const float* bk, const float* bv,
    bf16* q, bf16* k, bf16* v)
{
    const bf16* W = (blockIdx.z == 0) ? wq : (blockIdx.z == 1) ? wk : wv;
    const float* bias = (blockIdx.z == 0) ? bq : (blockIdx.z == 1) ? bk : bv;
    bf16* out = (blockIdx.z == 0) ? q : (blockIdx.z == 1) ? k : v;
    gemm_body<false, true>(xn, W, bias, nullptr, out, 0,
                           kTok, kC, kC, 1.0f, 0, 0, 0);
}

__global__ __launch_bounds__(256, 2) void gemm_nt_bf(
    const bf16* A, const bf16* B, const float* bias, bf16* C,
    int M, int N, int K, float alpha, s64 sA, s64 sB, s64 sC)
{
    gemm_body<false, true>(A, B, bias, nullptr, C, blockIdx.z,
                           M, N, K, alpha, sA, sB, sC);
}

__global__ __launch_bounds__(256, 2) void gemm_tt_bf(
    const bf16* A, const bf16* B, bf16* C,
    int M, int N, int K, float alpha, s64 sA, s64 sB, s64 sC)
{
    gemm_body<true, true>(A, B, nullptr, nullptr, C, blockIdx.z,
                          M, N, K, alpha, sA, sB, sC);
}

__global__ __launch_bounds__(256, 2) void gemm_nt_f32(
    const bf16* A, const bf16* B, const float* bias, const float* resid, float* C,
    int M, int N, int K, float alpha, s64 sA, s64 sB, s64 sC)
{
    gemm_body<false, false>(A, B, bias, resid, C, blockIdx.z,
                            M, N, K, alpha, sA, sB, sC);
}

// ---------------------------------------------------------------------------
// Row softmax over bf16 S (in-place), rows of 4096
// ---------------------------------------------------------------------------
__global__ __launch_bounds__(256) void softmax_kernel() {
    s64 row = blockIdx.x;
    uint4* p = (uint4*)(g_s + row * (s64)kSeq);
    int tid = threadIdx.x;

    uint4 raw[2];
    float vals[16];
    float mx = -1e30f;
    #pragma unroll
    for (int j = 0; j < 2; j++) {
        raw[j] = p[tid + 256 * j];
        const u32* w = (const u32*)&raw[j];
        #pragma unroll
        for (int q = 0; q < 4; q++) {
            float2 f = __bfloat1622float2(*(const __nv_bfloat162*)&w[q]);
            vals[j * 8 + q * 2 + 0] = f.x;
            vals[j * 8 + q * 2 + 1] = f.y;
            mx = fmaxf(mx, fmaxf(f.x, f.y));
        }
    }
    __shared__ float sh[8];
    int lane = tid & 31, wid = tid >> 5;
    mx = warp_max(mx);
    if (lane == 0) sh[wid] = mx;
    __syncthreads();
    mx = (lane < 8) ? sh[lane] : -1e30f;
    mx = warp_max(mx);
    mx = __shfl_sync(0xffffffffu, mx, 0);
    __syncthreads();

    float sum = 0.f;
    #pragma unroll
    for (int i = 0; i < 16; i++) {
        vals[i] = __expf(vals[i] - mx);
        sum += vals[i];
    }
    sum = warp_sum(sum);
    if (lane == 0) sh[wid] = sum;
    __syncthreads();
    sum = (lane < 8) ? sh[lane] : 0.f;
    sum = warp_sum(sum);
    sum = __shfl_sync(0xffffffffu, sum, 0);
    float inv = 1.0f / sum;

    #pragma unroll
    for (int j = 0; j < 2; j++) {
        u32* w = (u32*)&raw[j];
        #pragma unroll
        for (int q = 0; q < 4; q++) {
            __nv_bfloat162 pk = __floats2bfloat162_rn(
                vals[j * 8 + q * 2 + 0] * inv, vals[j * 8 + q * 2 + 1] * inv);
            w[q] = *(u32*)&pk;
        }
        p[tid + 256 * j] = raw[j];
    }
}

// ---------------------------------------------------------------------------
// Host orchestration
// ---------------------------------------------------------------------------
extern "C" void kernel_launch(void* const* d_in, const int* in_sizes, int n_in,
                              void* d_out, int out_size)
{
    const float* x     = (const float*)d_in[0];
    const float* gamma = (const float*)d_in[1];
    const float* beta  = (const float*)d_in[2];
    const float* Wq    = (const float*)d_in[3];
    const float* bq    = (const float*)d_in[4];
    const float* Wk    = (const float*)d_in[5];
    const float* bk    = (const float*)d_in[6];
    const float* Wv    = (const float*)d_in[7];
    const float* bv    = (const float*)d_in[8];
    const float* Wp    = (const float*)d_in[9];
    const float* bp    = (const float*)d_in[10];
    float* out = (float*)d_out;

    bf16 *p_xn = 0, *p_q = 0, *p_k = 0, *p_v = 0, *p_o = 0, *p_s = 0;
    bf16 *p_wq = 0, *p_wk = 0, *p_wv = 0, *p_wp = 0;
    cudaGetSymbolAddress((void**)&p_xn, g_xn);
    cudaGetSymbolAddress((void**)&p_q,  g_q);
    cudaGetSymbolAddress((void**)&p_k,  g_k);
    cudaGetSymbolAddress((void**)&p_v,  g_v);
    cudaGetSymbolAddress((void**)&p_o,  g_o);
    cudaGetSymbolAddress((void**)&p_s,  g_s);
    cudaGetSymbolAddress((void**)&p_wq, g_wq);
    cudaGetSymbolAddress((void**)&p_wk, g_wk);
    cudaGetSymbolAddress((void**)&p_wv, g_wv);
    cudaGetSymbolAddress((void**)&p_wp, g_wp);

    // opt-in dynamic smem above 48KB (host-side attr; not a stream op)
    cudaFuncSetAttribute(gemm_qkv,    cudaFuncAttributeMaxDynamicSharedMemorySize, SMEM_BYTES_N);
    cudaFuncSetAttribute(gemm_nt_bf,  cudaFuncAttributeMaxDynamicSharedMemorySize, SMEM_BYTES_N);
    cudaFuncSetAttribute(gemm_tt_bf,  cudaFuncAttributeMaxDynamicSharedMemorySize, SMEM_BYTES_T);
    cudaFuncSetAttribute(gemm_nt_f32, cudaFuncAttributeMaxDynamicSharedMemorySize, SMEM_BYTES_N);

    const s64 seqC = (s64)kSeq * kC;
    const s64 seqS = (s64)kSeq * kSeq;

    // 1) GroupNorm (+ bf16 conversion) and weight conversions
    gn_stats_kernel<<<kB * kGrp, 256>>>(x);
    gn_apply_kernel<<<(kTok * kC / 4) / 256, 256>>>(x, gamma, beta);
    dim3 gw((kC * kC / 4) / 256, 4, 1);
    f2bf_kernel<<<gw, 256>>>(Wq, Wk, Wv, Wp);

    // 2) Q, K, V projections fused into one launch (z selects projection)
    dim3 gqkv(kC / TBN, kTok / TBM, 3);
    gemm_qkv<<<gqkv, 256, SMEM_BYTES_N>>>(p_xn, p_wq, p_wk, p_wv,
                                          bq, bk, bv, p_q, p_k, p_v);

    // 3) S = Q @ K^T * 1/sqrt(C) per batch -> bf16
    const float scale = 0.044194173824159216f;   // 1/sqrt(512)
    dim3 gqk(kSeq / TBN, kSeq / TBM, kB);
    gemm_tt_bf<<<gqk, 256, SMEM_BYTES_T>>>(p_q, p_k, p_s, kSeq, kSeq, kC, scale,
                                           seqC, seqC, seqS);

    // 4) softmax rows (bf16 in-place)
    softmax_kernel<<<kB * kSeq, 256>>>();

    // 5) O = P @ V per batch -> bf16
    dim3 gpv(kC / TBN, kSeq / TBM, kB);
    gemm_nt_bf<<<gpv, 256, SMEM_BYTES_N>>>(p_s, p_v, nullptr, p_o,
                                           kSeq, kC, kSeq, 1.0f,
                                           seqS, seqC, seqC);

    // 6) out = O @ Wp + bp + inputs (fp32)
    dim3 gproj(kC / TBN, kTok / TBM, 1);
    gemm_nt_f32<<<gproj, 256, SMEM_BYTES_N>>>(p_o, p_wp, bp, x, out,
                                              kTok, kC, kC, 1.0f, 0, 0, 0);
}

// round 13
// speedup vs baseline: 1.3071x; 1.1938x over previous
#include <cuda_runtime.h>
#include <cuda_bf16.h>
#include <math.h>

using bf16 = __nv_bfloat16;
using u32  = unsigned int;
using s64  = long long;

// ---------------------------------------------------------------------------
// Problem constants
// ---------------------------------------------------------------------------
constexpr int kB    = 2;
constexpr int kC    = 512;
constexpr int kGrp  = 32;
constexpr int kSeq  = 4096;
constexpr int kTok  = 8192;
constexpr float kEps = 1e-5f;

// ---------------------------------------------------------------------------
// GEMM tiling: 128x128 CTA tile, 4 warps (2x2), 64x64 warp tile, K=32/stage,
// 3-stage cp.async ring, 128 threads, occupancy 2.
// ---------------------------------------------------------------------------
constexpr int TBM = 128;
constexpr int TBN = 128;
constexpr int TBK = 32;
constexpr int APAD   = TBK + 8;   // 40
constexpr int BPAD_T = TBK + 8;   // 40  (TB: rows = N)
constexpr int BPAD_N = TBN + 8;   // 136 (non-TB: rows = K)

constexpr int STAGES = 3;
constexpr int ASZ   = TBM * APAD;     // 5120 elems / stage
constexpr int BSZ_T = TBN * BPAD_T;   // 5120
constexpr int BSZ_N = TBK * BPAD_N;   // 4352
constexpr int SMEM_BYTES_T = STAGES * (ASZ + BSZ_T) * 2;   // 61440
constexpr int SMEM_BYTES_N = STAGES * (ASZ + BSZ_N) * 2;   // 56832

// ---------------------------------------------------------------------------
// Device scratch (allocation-free rule: __device__ globals)
// ---------------------------------------------------------------------------
__device__ __align__(128) bf16 g_xn[kTok * kC];
__device__ __align__(128) bf16 g_q [kTok * kC];
__device__ __align__(128) bf16 g_k [kTok * kC];
__device__ __align__(128) bf16 g_v [kTok * kC];
__device__ __align__(128) bf16 g_o [kTok * kC];
__device__ __align__(128) bf16 g_s [(s64)kB * kSeq * kSeq];   // 64 MB
__device__ __align__(128) bf16 g_wq[kC * kC];
__device__ __align__(128) bf16 g_wk[kC * kC];
__device__ __align__(128) bf16 g_wv[kC * kC];
__device__ __align__(128) bf16 g_wp[kC * kC];
__device__ float g_mu  [kB * kGrp];
__device__ float g_rsig[kB * kGrp];

// ---------------------------------------------------------------------------
// Small helpers
// ---------------------------------------------------------------------------
__device__ __forceinline__ float warp_sum(float v) {
    #pragma unroll
    for (int o = 16; o > 0; o >>= 1) v += __shfl_xor_sync(0xffffffffu, v, o);
    return v;
}
__device__ __forceinline__ float warp_max(float v) {
    #pragma unroll
    for (int o = 16; o > 0; o >>= 1) v = fmaxf(v, __shfl_xor_sync(0xffffffffu, v, o));
    return v;
}

__device__ __forceinline__ u32 smem_u32(const void* p) {
    return (u32)__cvta_generic_to_shared(p);
}
__device__ __forceinline__ void cpasync16(u32 s, const void* g) {
    asm volatile("cp.async.cg.shared.global [%0], [%1], 16;" :: "r"(s), "l"(g));
}
__device__ __forceinline__ void cp_commit() { asm volatile("cp.async.commit_group;"); }
__device__ __forceinline__ void cp_wait0()  { asm volatile("cp.async.wait_group 0;"); }
__device__ __forceinline__ void cp_wait1()  { asm volatile("cp.async.wait_group 1;"); }

__device__ __forceinline__ void ldm_x4(u32& r0, u32& r1, u32& r2, u32& r3, u32 a) {
    asm volatile("ldmatrix.sync.aligned.m8n8.x4.shared.b16 {%0,%1,%2,%3}, [%4];"
                 : "=r"(r0), "=r"(r1), "=r"(r2), "=r"(r3) : "r"(a));
}
__device__ __forceinline__ void ldm_x4t(u32& r0, u32& r1, u32& r2, u32& r3, u32 a) {
    asm volatile("ldmatrix.sync.aligned.m8n8.x4.trans.shared.b16 {%0,%1,%2,%3}, [%4];"
                 : "=r"(r0), "=r"(r1), "=r"(r2), "=r"(r3) : "r"(a));
}
__device__ __forceinline__ void mma16816(float* c, const u32* a, const u32* b) {
    asm volatile(
        "mma.sync.aligned.m16n8k16.row.col.f32.bf16.bf16.f32 "
        "{%0,%1,%2,%3}, {%4,%5,%6,%7}, {%8,%9}, {%0,%1,%2,%3};"
        : "+f"(c[0]), "+f"(c[1]), "+f"(c[2]), "+f"(c[3])
        : "r"(a[0]), "r"(a[1]), "r"(a[2]), "r"(a[3]), "r"(b[0]), "r"(b[1]));
}

// ---------------------------------------------------------------------------
// GroupNorm statistics: one block per (b, g)
// ---------------------------------------------------------------------------
__global__ __launch_bounds__(256) void gn_stats_kernel(const float* __restrict__ x) {
    int bg = blockIdx.x;
    int b  = bg >> 5;
    int g  = bg & 31;
    const float* base = x + (s64)b * kSeq * kC + g * 16;

    float s = 0.f, s2 = 0.f;
    for (int t4 = threadIdx.x; t4 < kSeq * 4; t4 += 256) {
        int hw = t4 >> 2, j4 = t4 & 3;
        float4 v = *(const float4*)(base + (s64)hw * kC + j4 * 4);
        s  += v.x + v.y + v.z + v.w;
        s2 += v.x*v.x + v.y*v.y + v.z*v.z + v.w*v.w;
    }
    __shared__ float sh_s[8], sh_s2[8];
    int lane = threadIdx.x & 31, wid = threadIdx.x >> 5;
    s = warp_sum(s); s2 = warp_sum(s2);
    if (lane == 0) { sh_s[wid] = s; sh_s2[wid] = s2; }
    __syncthreads();
    if (wid == 0) {
        s  = (lane < 8) ? sh_s[lane]  : 0.f;
        s2 = (lane < 8) ? sh_s2[lane] : 0.f;
        s = warp_sum(s); s2 = warp_sum(s2);
        if (lane == 0) {
            float inv = 1.0f / (float)(kSeq * 16);
            float m = s * inv;
            float var = s2 * inv - m * m;
            g_mu[bg]   = m;
            g_rsig[bg] = rsqrtf(var + kEps);
        }
    }
}

// ---------------------------------------------------------------------------
// GroupNorm apply -> bf16 xn
// ---------------------------------------------------------------------------
__global__ __launch_bounds__(256) void gn_apply_kernel(
    const float* __restrict__ x, const float* __restrict__ gamma,
    const float* __restrict__ beta)
{
    s64 i4 = (s64)blockIdx.x * 256 + threadIdx.x;   // float4 index
    int c4 = (int)(i4 & 127);
    int b  = (int)(i4 >> 19);
    int g  = c4 >> 2;
    float m = g_mu[b * kGrp + g];
    float r = g_rsig[b * kGrp + g];
    float4 xv = ((const float4*)x)[i4];
    float4 gv = ((const float4*)gamma)[c4];
    float4 bv = ((const float4*)beta)[c4];
    float o0 = (xv.x - m) * r * gv.x + bv.x;
    float o1 = (xv.y - m) * r * gv.y + bv.y;
    float o2 = (xv.z - m) * r * gv.z + bv.z;
    float o3 = (xv.w - m) * r * gv.w + bv.w;
    __nv_bfloat162 p0 = __floats2bfloat162_rn(o0, o1);
    __nv_bfloat162 p1 = __floats2bfloat162_rn(o2, o3);
    uint2 pk;
    pk.x = *(u32*)&p0;
    pk.y = *(u32*)&p1;
    ((uint2*)g_xn)[i4] = pk;
}

// ---------------------------------------------------------------------------
// fp32 -> bf16 conversion (weights); blockIdx.y selects which of 4 weights
// ---------------------------------------------------------------------------
__global__ __launch_bounds__(256) void f2bf_kernel(
    const float* __restrict__ w0, const float* __restrict__ w1,
    const float* __restrict__ w2, const float* __restrict__ w3)
{
    const float* src = (blockIdx.y == 0) ? w0 : (blockIdx.y == 1) ? w1
                     : (blockIdx.y == 2) ? w2 : w3;
    bf16* dst = (blockIdx.y == 0) ? g_wq : (blockIdx.y == 1) ? g_wk
              : (blockIdx.y == 2) ? g_wv : g_wp;
    s64 i4 = (s64)blockIdx.x * 256 + threadIdx.x;
    float4 v = ((const float4*)src)[i4];
    __nv_bfloat162 p0 = __floats2bfloat162_rn(v.x, v.y);
    __nv_bfloat162 p1 = __floats2bfloat162_rn(v.z, v.w);
    uint2 pk;
    pk.x = *(u32*)&p0;
    pk.y = *(u32*)&p1;
    ((uint2*)dst)[i4] = pk;
}

// ---------------------------------------------------------------------------
// Stage loader (flat smem, 128 threads): As [128][40],
// Bs TB [128][40] / non-TB [32][136]
// ---------------------------------------------------------------------------
template<bool TB>
__device__ __forceinline__ void load_stage_fn(
    bf16* As, bf16* Bs, const bf16* A, const bf16* B,
    int m0, int n0, int K, int N, int k0, int tid)
{
    #pragma unroll
    for (int i = 0; i < 4; i++) {
        int c = tid + 128 * i;                 // 512 16B chunks cover 128x32
        int r = c >> 2, cc = c & 3;
        cpasync16(smem_u32(As + r * APAD + cc * 8),
                  A + (s64)(m0 + r) * K + k0 + cc * 8);
    }
    #pragma unroll
    for (int i = 0; i < 4; i++) {
        int c = tid + 128 * i;
        if (TB) {
            int r = c >> 2, cc = c & 3;        // r: n-row, cc: k-chunk
            cpasync16(smem_u32(Bs + r * BPAD_T + cc * 8),
                      B + (s64)(n0 + r) * K + k0 + cc * 8);
        } else {
            int r = c >> 4, cc = c & 15;       // r: k-row, cc: n-chunk
            cpasync16(smem_u32(Bs + r * BPAD_N + cc * 8),
                      B + (s64)(k0 + r) * N + n0 + cc * 8);
        }
    }
    cp_commit();
}

// ---------------------------------------------------------------------------
// GEMM body: C = alpha * A @ op(B) [+ bias] [+ resid]
//   A: [M,K] bf16 row-major.  B: TB ? [N,K] : [K,N] bf16 row-major.
//   128x128x32 CTA tile, 128 threads = 2(M) x 2(N) warps, 64x64 per warp.
//   3-stage cp.async ring, one __syncthreads per K-tile. Dynamic smem.
// ---------------------------------------------------------------------------
extern __shared__ bf16 dynsmem[];

template<bool TB, bool OUTBF>
__device__ __forceinline__ void gemm_body(
    const bf16* A, const bf16* B,
    const float* bias, const float* resid, void* Cout,
    int bz, int M, int N, int K, float alpha, s64 sA, s64 sB, s64 sC)
{
    constexpr int BSZ = TB ? BSZ_T : BSZ_N;
    constexpr int BP  = TB ? BPAD_T : BPAD_N;
    bf16* As = dynsmem;
    bf16* Bs = dynsmem + STAGES * ASZ;

    A += bz * sA;
    B += bz * sB;

    int m0 = blockIdx.y * TBM;
    int n0 = blockIdx.x * TBN;
    int tid = threadIdx.x;
    int lane = tid & 31, wid = tid >> 5;
    int wm = wid & 1;          // 2 warps along M (64 rows each)
    int wn = wid >> 1;         // 2 warps along N (64 cols each)

    float acc[4][8][4];
    #pragma unroll
    for (int i = 0; i < 4; i++)
        #pragma unroll
        for (int j = 0; j < 8; j++)
            #pragma unroll
            for (int q = 0; q < 4; q++) acc[i][j][q] = 0.f;

    const int KT = K / TBK;    // >= 16 for every call here

    // prologue: stages 0 and 1 in flight
    load_stage_fn<TB>(As, Bs, A, B, m0, n0, K, N, 0, tid);
    load_stage_fn<TB>(As + ASZ, Bs + BSZ, A, B, m0, n0, K, N, TBK, tid);
    cp_wait1();                // stage 0 complete
    __syncthreads();

    int cur = 0;
    for (int kt = 0; kt < KT; kt++) {
        bool issue = (kt + 2 < KT);
        if (issue) {
            int nx = cur + 2; if (nx >= STAGES) nx -= STAGES;
            load_stage_fn<TB>(As + nx * ASZ, Bs + nx * BSZ, A, B,
                              m0, n0, K, N, (kt + 2) * TBK, tid);
        }

        const bf16* as = As + cur * ASZ;
        const bf16* bs = Bs + cur * BSZ;

        #pragma unroll
        for (int ks = 0; ks < 2; ks++) {
            u32 a[4][4];
            #pragma unroll
            for (int mf = 0; mf < 4; mf++) {
                int row = wm * 64 + mf * 16 + (lane & 15);
                int col = ks * 16 + ((lane >> 4) << 3);
                ldm_x4(a[mf][0], a[mf][1], a[mf][2], a[mf][3],
                       smem_u32(as + row * APAD + col));
            }
            u32 b[8][2];
            #pragma unroll
            for (int p = 0; p < 4; p++) {     // nf pair {2p, 2p+1}
                if (TB) {
                    // lane-group m: m>>1 selects nf offset, m&1 selects k-half
                    int mgrp = lane >> 3;
                    int row = wn * 64 + (2 * p + (mgrp >> 1)) * 8 + (lane & 7);
                    int col = ks * 16 + (mgrp & 1) * 8;
                    ldm_x4(b[2*p][0], b[2*p][1], b[2*p+1][0], b[2*p+1][1],
                           smem_u32(bs + row * BP + col));
                } else {
                    // trans: lanes 0-15 -> nf=2p, lanes 16-31 -> nf=2p+1
                    int row = ks * 16 + (lane & 15);
                    int col = wn * 64 + (2 * p + (lane >> 4)) * 8;
                    ldm_x4t(b[2*p][0], b[2*p][1], b[2*p+1][0], b[2*p+1][1],
                            smem_u32(bs + row * BP + col));
                }
            }
            #pragma unroll
            for (int mf = 0; mf < 4; mf++)
                #pragma unroll
                for (int nf = 0; nf < 8; nf++)
                    mma16816(acc[mf][nf], a[mf], b[nf]);
        }

        if (issue) cp_wait1(); else cp_wait0();
        __syncthreads();
        cur++; if (cur >= STAGES) cur = 0;
    }

    // ---- epilogue ----
    #pragma unroll
    for (int mf = 0; mf < 4; mf++) {
        #pragma unroll
        for (int nf = 0; nf < 8; nf++) {
            int r0 = m0 + wm * 64 + mf * 16 + (lane >> 2);
            int c  = n0 + wn * 64 + nf * 8 + ((lane & 3) << 1);
            float bx = 0.f, by = 0.f;
            if (bias) { bx = bias[c]; by = bias[c + 1]; }
            #pragma unroll
            for (int h = 0; h < 2; h++) {
                int m = r0 + h * 8;
                float v0 = acc[mf][nf][h * 2 + 0] * alpha + bx;
                float v1 = acc[mf][nf][h * 2 + 1] * alpha + by;
                s64 off = (s64)m * N + c;
                if (OUTBF) {
                    __nv_bfloat162 p = __floats2bfloat162_rn(v0, v1);
                    *(u32*)((bf16*)Cout + bz * sC + off) = *(u32*)&p;
                } else {
                    if (resid) {
                        float2 rv = *(const float2*)(resid + bz * sC + off);
                        v0 += rv.x; v1 += rv.y;
                    }
                    float2 o2; o2.x = v0; o2.y = v1;
                    *(float2*)((float*)Cout + bz * sC + off) = o2;
                }
            }
        }
    }
}

// ---------------------------------------------------------------------------
// Concrete kernels (plain names at launch sites)
// ---------------------------------------------------------------------------
// Fused Q/K/V projections: blockIdx.z selects which projection
__global__ __launch_bounds__(128, 2) void gemm_qkv(
    const bf16* xn,
    const bf16* wq, const bf16* wk, const bf16* wv,
    const float* bq, const float* bk, const float* bv,
    bf16* q, bf16* k, bf16* v)
{
    const bf16* W = (blockIdx.z == 0) ? wq : (blockIdx.z == 1) ? wk : wv;
    const float* bias = (blockIdx.z == 0) ? bq : (blockIdx.z == 1) ? bk : bv;
    bf16* out = (blockIdx.z == 0) ? q : (blockIdx.z == 1) ? k : v;
    gemm_body<false, true>(xn, W, bias, nullptr, out, 0,
                           kTok, kC, kC, 1.0f, 0, 0, 0);
}

__global__ __launch_bounds__(128, 2) void gemm_nt_bf(
    const bf16* A, const bf16* B, const float* bias, bf16* C,
    int M, int N, int K, float alpha, s64 sA, s64 sB, s64 sC)
{
    gemm_body<false, true>(A, B, bias, nullptr, C, blockIdx.z,
                           M, N, K, alpha, sA, sB, sC);
}

__global__ __launch_bounds__(128, 2) void gemm_tt_bf(
    const bf16* A, const bf16* B, bf16* C,
    int M, int N, int K, float alpha, s64 sA, s64 sB, s64 sC)
{
    gemm_body<true, true>(A, B, nullptr, nullptr, C, blockIdx.z,
                          M, N, K, alpha, sA, sB, sC);
}

__global__ __launch_bounds__(128, 2) void gemm_nt_f32(
    const bf16* A, const bf16* B, const float* bias, const float* resid, float* C,
    int M, int N, int K, float alpha, s64 sA, s64 sB, s64 sC)
{
    gemm_body<false, false>(A, B, bias, resid, C, blockIdx.z,
                            M, N, K, alpha, sA, sB, sC);
}

// ---------------------------------------------------------------------------
// Row softmax over bf16 S (in-place), rows of 4096
// ---------------------------------------------------------------------------
__global__ __launch_bounds__(256) void softmax_kernel() {
    s64 row = blockIdx.x;
    uint4* p = (uint4*)(g_s + row * (s64)kSeq);
    int tid = threadIdx.x;

    uint4 raw[2];
    float vals[16];
    float mx = -1e30f;
    #pragma unroll
    for (int j = 0; j < 2; j++) {
        raw[j] = p[tid + 256 * j];
        const u32* w = (const u32*)&raw[j];
        #pragma unroll
        for (int q = 0; q < 4; q++) {
            float2 f = __bfloat1622float2(*(const __nv_bfloat162*)&w[q]);
            vals[j * 8 + q * 2 + 0] = f.x;
            vals[j * 8 + q * 2 + 1] = f.y;
            mx = fmaxf(mx, fmaxf(f.x, f.y));
        }
    }
    __shared__ float sh[8];
    int lane = tid & 31, wid = tid >> 5;
    mx = warp_max(mx);
    if (lane == 0) sh[wid] = mx;
    __syncthreads();
    mx = (lane < 8) ? sh[lane] : -1e30f;
    mx = warp_max(mx);
    mx = __shfl_sync(0xffffffffu, mx, 0);
    __syncthreads();

    float sum = 0.f;
    #pragma unroll
    for (int i = 0; i < 16; i++) {
        vals[i] = __expf(vals[i] - mx);
        sum += vals[i];
    }
    sum = warp_sum(sum);
    if (lane == 0) sh[wid] = sum;
    __syncthreads();
    sum = (lane < 8) ? sh[lane] : 0.f;
    sum = warp_sum(sum);
    sum = __shfl_sync(0xffffffffu, sum, 0);
    float inv = 1.0f / sum;

    #pragma unroll
    for (int j = 0; j < 2; j++) {
        u32* w = (u32*)&raw[j];
        #pragma unroll
        for (int q = 0; q < 4; q++) {
            __nv_bfloat162 pk = __floats2bfloat162_rn(
                vals[j * 8 + q * 2 + 0] * inv, vals[j * 8 + q * 2 + 1] * inv);
            w[q] = *(u32*)&pk;
        }
        p[tid + 256 * j] = raw[j];
    }
}

// ---------------------------------------------------------------------------
// Host orchestration
// ---------------------------------------------------------------------------
extern "C" void kernel_launch(void* const* d_in, const int* in_sizes, int n_in,
                              void* d_out, int out_size)
{
    const float* x     = (const float*)d_in[0];
    const float* gamma = (const float*)d_in[1];
    const float* beta  = (const float*)d_in[2];
    const float* Wq    = (const float*)d_in[3];
    const float* bq    = (const float*)d_in[4];
    const float* Wk    = (const float*)d_in[5];
    const float* bk    = (const float*)d_in[6];
    const float* Wv    = (const float*)d_in[7];
    const float* bv    = (const float*)d_in[8];
    const float* Wp    = (const float*)d_in[9];
    const float* bp    = (const float*)d_in[10];
    float* out = (float*)d_out;

    bf16 *p_xn = 0, *p_q = 0, *p_k = 0, *p_v = 0, *p_o = 0, *p_s = 0;
    bf16 *p_wq = 0, *p_wk = 0, *p_wv = 0, *p_wp = 0;
    cudaGetSymbolAddress((void**)&p_xn, g_xn);
    cudaGetSymbolAddress((void**)&p_q,  g_q);
    cudaGetSymbolAddress((void**)&p_k,  g_k);
    cudaGetSymbolAddress((void**)&p_v,  g_v);
    cudaGetSymbolAddress((void**)&p_o,  g_o);
    cudaGetSymbolAddress((void**)&p_s,  g_s);
    cudaGetSymbolAddress((void**)&p_wq, g_wq);
    cudaGetSymbolAddress((void**)&p_wk, g_wk);
    cudaGetSymbolAddress((void**)&p_wv, g_wv);
    cudaGetSymbolAddress((void**)&p_wp, g_wp);

    // opt-in dynamic smem above 48KB (host-side attr; not a stream op)
    cudaFuncSetAttribute(gemm_qkv,    cudaFuncAttributeMaxDynamicSharedMemorySize, SMEM_BYTES_N);
    cudaFuncSetAttribute(gemm_nt_bf,  cudaFuncAttributeMaxDynamicSharedMemorySize, SMEM_BYTES_N);
    cudaFuncSetAttribute(gemm_tt_bf,  cudaFuncAttributeMaxDynamicSharedMemorySize, SMEM_BYTES_T);
    cudaFuncSetAttribute(gemm_nt_f32, cudaFuncAttributeMaxDynamicSharedMemorySize, SMEM_BYTES_N);

    const s64 seqC = (s64)kSeq * kC;
    const s64 seqS = (s64)kSeq * kSeq;

    // 1) GroupNorm (+ bf16 conversion) and weight conversions
    gn_stats_kernel<<<kB * kGrp, 256>>>(x);
    gn_apply_kernel<<<(kTok * kC / 4) / 256, 256>>>(x, gamma, beta);
    dim3 gw((kC * kC / 4) / 256, 4, 1);
    f2bf_kernel<<<gw, 256>>>(Wq, Wk, Wv, Wp);

    // 2) Q, K, V projections fused into one launch (z selects projection)
    dim3 gqkv(kC / TBN, kTok / TBM, 3);
    gemm_qkv<<<gqkv, 128, SMEM_BYTES_N>>>(p_xn, p_wq, p_wk, p_wv,
                                          bq, bk, bv, p_q, p_k, p_v);

    // 3) S = Q @ K^T * 1/sqrt(C) per batch -> bf16
    const float scale = 0.044194173824159216f;   // 1/sqrt(512)
    dim3 gqk(kSeq / TBN, kSeq / TBM, kB);
    gemm_tt_bf<<<gqk, 128, SMEM_BYTES_T>>>(p_q, p_k, p_s, kSeq, kSeq, kC, scale,
                                           seqC, seqC, seqS);

    // 4) softmax rows (bf16 in-place)
    softmax_kernel<<<kB * kSeq, 256>>>();

    // 5) O = P @ V per batch -> bf16
    dim3 gpv(kC / TBN, kSeq / TBM, kB);
    gemm_nt_bf<<<gpv, 128, SMEM_BYTES_N>>>(p_s, p_v, nullptr, p_o,
                                           kSeq, kC, kSeq, 1.0f,
                                           seqS, seqC, seqC);

    // 6) out = O @ Wp + bp + inputs (fp32)
    dim3 gproj(kC / TBN, kTok / TBM, 1);
    gemm_nt_f32<<<gproj, 128, SMEM_BYTES_N>>>(p_o, p_wp, bp, x, out,
                                              kTok, kC, kC, 1.0f, 0, 0, 0);
}